// round 2
// baseline (speedup 1.0000x reference)
#include <cuda_runtime.h>
#include <math.h>

#define Nn 16384
#define Ee 262144
#define Tt 4
#define Dd 64
#define Ll 2
#define TND (Tt*Nn*Dd)

// ---- scratch (static __device__, allocation-free) ----
__device__ int   g_rowr[Ee], g_colr[Ee], g_etr[Ee];   // decoded edges
__device__ int   g_scol[Ee], g_set[Ee];               // CSR-sorted col / edge-type
__device__ int   g_deg[Nn], g_off[Nn + 1], g_cur[Nn];
__device__ float g_h[TND];                            // current node features (T,N,D)
__device__ float g_hw[TND];                           // h @ we  (T,N,D)
__device__ float g_si[Tt * Nn], g_sj[Tt * Nn];        // per-node logit dots
__device__ float g_p[Tt * Ee];                        // unnormalized exp per sorted edge
__device__ float g_den[Tt * Nn];                      // softmax denominators
__device__ float g_ef[Tt * Dd];                       // current edge features
__device__ float g_rg[Tt * Tt];
__device__ float g_vg[Tt * Dd];                       // sigmoid(ef @ wr)
__device__ int   g_is64;                              // 1 if edge arrays are int64

// ---- dtype detect: int64 data is always in [0,N); int32 read as int64 is not ----
__global__ void k_detect(const void* eidx) {
    if (threadIdx.x != 0 || blockIdx.x != 0) return;
    const long long* p = (const long long*)eidx;
    int ok = 1;
    for (int i = 0; i < 1024; i++) {
        long long v = p[i];
        if (v < 0 || v >= Nn) { ok = 0; break; }
    }
    g_is64 = ok;
}

// ---- setup: init h (broadcast x), ef, zero degree histogram ----
__global__ void k_init(const float* __restrict__ x, const float* __restrict__ ef0) {
    int i = blockIdx.x * blockDim.x + threadIdx.x;
    int stride = gridDim.x * blockDim.x;
    for (int j = i; j < TND; j += stride) {
        int nd = j & (Nn * Dd - 1);   // Nn*Dd is power of 2
        g_h[j] = x[nd];
    }
    if (i < Tt * Dd) g_ef[i] = ef0[i];
    for (int j = i; j < Nn; j += stride) g_deg[j] = 0;
}

__global__ void k_hist(const void* __restrict__ eidx, const void* __restrict__ etyp) {
    int e = blockIdx.x * blockDim.x + threadIdx.x;
    if (e >= Ee) return;
    int r, c, t;
    if (g_is64) {
        r = (int)((const long long*)eidx)[e];
        c = (int)((const long long*)eidx)[Ee + e];
        t = (int)((const long long*)etyp)[e];
    } else {
        r = ((const int*)eidx)[e];
        c = ((const int*)eidx)[Ee + e];
        t = ((const int*)etyp)[e];
    }
    g_rowr[e] = r; g_colr[e] = c; g_etr[e] = t;
    atomicAdd(&g_deg[r], 1);
}

// single block, 1024 threads, 16 elems each -> exclusive scan of 16384 degrees
__global__ void k_scan() {
    __shared__ int sh[1024];
    int tid = threadIdx.x;
    int base = tid * 16;
    int loc[16];
    int tot = 0;
#pragma unroll
    for (int i = 0; i < 16; i++) { loc[i] = tot; tot += g_deg[base + i]; }
    sh[tid] = tot;
    __syncthreads();
    for (int off = 1; off < 1024; off <<= 1) {
        int v = (tid >= off) ? sh[tid - off] : 0;
        __syncthreads();
        sh[tid] += v;
        __syncthreads();
    }
    int pre = (tid == 0) ? 0 : sh[tid - 1];
#pragma unroll
    for (int i = 0; i < 16; i++) {
        g_off[base + i] = pre + loc[i];
        g_cur[base + i] = pre + loc[i];
    }
    if (tid == 1023) g_off[Nn] = pre + tot;
}

__global__ void k_scatter() {
    int e = blockIdx.x * blockDim.x + threadIdx.x;
    if (e >= Ee) return;
    int pos = atomicAdd(&g_cur[g_rowr[e]], 1);
    g_scol[pos] = g_colr[e];
    g_set[pos]  = g_etr[e];
}

// ---- per-layer tiny math: rg = tg @ ef^T ; ef' = ef @ wr ; vg = sigmoid(ef') ----
__global__ void k_rgef(const float* __restrict__ theta, const float* __restrict__ wr, int layer) {
    __shared__ float ef_s[Tt * Dd];
    int tid = threadIdx.x;              // 256 threads
    ef_s[tid] = g_ef[tid];
    __syncthreads();
    const float* th = theta + (size_t)layer * Tt * 3 * Dd;
    if (tid < Tt * Tt) {
        int t1 = tid >> 2, t2 = tid & 3;
        const float* tg = th + t1 * 3 * Dd;
        float s = 0.f;
#pragma unroll
        for (int k = 0; k < Dd; k++) s += tg[k] * ef_s[t2 * Dd + k];
        g_rg[tid] = s;
    }
    {
        int t = tid >> 6, d = tid & 63;
        const float* w = wr + (size_t)layer * Dd * Dd;
        float s = 0.f;
#pragma unroll
        for (int k = 0; k < Dd; k++) s += ef_s[t * Dd + k] * w[k * Dd + d];
        g_vg[tid] = 1.f / (1.f + __expf(-s));
        g_ef[tid] = (layer < Ll - 1) ? fmaxf(s, 0.f) : s;   // relu for next layer
    }
}

// ---- hw[t,n,:] = h[t,n,:] @ we[layer]  (32 nodes per block, per type) ----
__global__ void k_gemm(const float* __restrict__ we, int layer) {
    __shared__ float we_s[Dd * Dd];
    __shared__ float h_s[32 * Dd];
    int tid = threadIdx.x;              // 256
    int t = blockIdx.y;
    int n0 = blockIdx.x * 32;
    const float* w = we + (size_t)layer * Dd * Dd;
#pragma unroll
    for (int i = 0; i < 16; i++) we_s[tid + i * 256] = w[tid + i * 256];
    const float* hb = g_h + (size_t)t * Nn * Dd + (size_t)n0 * Dd;
#pragma unroll
    for (int i = 0; i < 8; i++) h_s[tid + i * 256] = hb[tid + i * 256];
    __syncthreads();
    int d = tid & 63, ng = tid >> 6;    // ng in 0..3 -> nodes ng*8..ng*8+7
    float acc[8] = {0.f, 0.f, 0.f, 0.f, 0.f, 0.f, 0.f, 0.f};
#pragma unroll
    for (int k = 0; k < Dd; k++) {
        float wv = we_s[k * Dd + d];
#pragma unroll
        for (int j = 0; j < 8; j++) acc[j] += h_s[(ng * 8 + j) * Dd + k] * wv;
    }
    float* ob = g_hw + (size_t)t * Nn * Dd + (size_t)n0 * Dd;
#pragma unroll
    for (int j = 0; j < 8; j++) ob[(ng * 8 + j) * Dd + d] = acc[j];
}

// ---- si/sj dots: warp per (t,n) ----
__global__ void k_dots(const float* __restrict__ theta, int layer) {
    int w = (blockIdx.x * blockDim.x + threadIdx.x) >> 5;
    int lane = threadIdx.x & 31;
    int t = w / Nn, n = w - t * Nn;
    const float* hp = g_h + (size_t)t * Nn * Dd + (size_t)n * Dd;
    const float* th = theta + (size_t)layer * Tt * 3 * Dd + t * 3 * Dd;
    float a = hp[lane], b = hp[lane + 32];
    float si = a * th[Dd + lane] + b * th[Dd + lane + 32];
    float sj = a * th[2 * Dd + lane] + b * th[2 * Dd + lane + 32];
#pragma unroll
    for (int o = 16; o; o >>= 1) {
        si += __shfl_down_sync(0xffffffffu, si, o);
        sj += __shfl_down_sync(0xffffffffu, sj, o);
    }
    if (lane == 0) { g_si[t * Nn + n] = si; g_sj[t * Nn + n] = sj; }
}

// ---- scatter softmax: warp per node over its CSR segment ----
__global__ void k_soft() {
    __shared__ float rg_s[Tt * Tt];
    if (threadIdx.x < Tt * Tt) rg_s[threadIdx.x] = g_rg[threadIdx.x];
    __syncthreads();
    int warp = threadIdx.x >> 5, lane = threadIdx.x & 31;
    int n = blockIdx.x * 4 + warp;
    int beg = g_off[n], end = g_off[n + 1];
    float siv[Tt];
#pragma unroll
    for (int t = 0; t < Tt; t++) siv[t] = g_si[t * Nn + n];
    float m[Tt] = {-3.4e38f, -3.4e38f, -3.4e38f, -3.4e38f};
    for (int e = beg + lane; e < end; e += 32) {
        int c = g_scol[e], ty = g_set[e];
#pragma unroll
        for (int t = 0; t < Tt; t++) {
            float l = rg_s[t * 4 + ty] + siv[t] + g_sj[t * Nn + c];
            m[t] = fmaxf(m[t], l);
        }
    }
#pragma unroll
    for (int t = 0; t < Tt; t++)
#pragma unroll
        for (int o = 16; o; o >>= 1) m[t] = fmaxf(m[t], __shfl_xor_sync(0xffffffffu, m[t], o));
    float s[Tt] = {0.f, 0.f, 0.f, 0.f};
    for (int e = beg + lane; e < end; e += 32) {
        int c = g_scol[e], ty = g_set[e];
#pragma unroll
        for (int t = 0; t < Tt; t++) {
            float l = rg_s[t * 4 + ty] + siv[t] + g_sj[t * Nn + c];
            float p = __expf(l - m[t]);
            s[t] += p;
            g_p[t * Ee + e] = p;      // unnormalized
        }
    }
#pragma unroll
    for (int t = 0; t < Tt; t++)
#pragma unroll
        for (int o = 16; o; o >>= 1) s[t] += __shfl_xor_sync(0xffffffffu, s[t], o);
    if (lane == 0) {
#pragma unroll
        for (int t = 0; t < Tt; t++) g_den[t * Nn + n] = s[t];
    }
}

// ---- aggregation: block(64) per node, atomic-free, normalize at the end ----
__global__ void k_agg(float* __restrict__ out, int final_layer, int dorelu) {
    __shared__ float vg_s[Tt * Dd];
    int d = threadIdx.x;                // 64
#pragma unroll
    for (int i = 0; i < 4; i++) vg_s[d + i * 64] = g_vg[d + i * 64];
    __syncthreads();
    int n = blockIdx.x;
    int beg = g_off[n], end = g_off[n + 1];
    float acc[Tt] = {0.f, 0.f, 0.f, 0.f};
    for (int e = beg; e < end; e++) {
        int c = g_scol[e], ty = g_set[e];
        const float* vg = vg_s + ty * Dd + d;
#pragma unroll
        for (int t = 0; t < Tt; t++) {
            float p = g_p[t * Ee + e];
            acc[t] += p * vg[0] * g_hw[(size_t)t * (Nn * Dd) + (size_t)c * Dd + d];
        }
    }
    float* dst = final_layer ? out : g_h;
#pragma unroll
    for (int t = 0; t < Tt; t++) {
        float den = g_den[t * Nn + n];
        float inv = den > 0.f ? 1.f / den : 0.f;
        float v = acc[t] * inv;
        if (dorelu) v = fmaxf(v, 0.f);
        dst[(size_t)t * (Nn * Dd) + (size_t)n * Dd + d] = v;
    }
}

extern "C" void kernel_launch(void* const* d_in, const int* in_sizes, int n_in,
                              void* d_out, int out_size) {
    const float* x     = (const float*)d_in[0];
    const float* ef0   = (const float*)d_in[1];
    const float* theta = (const float*)d_in[2];
    const float* wr    = (const float*)d_in[3];
    const float* we    = (const float*)d_in[4];
    const void*  eidx  = d_in[5];
    const void*  etyp  = d_in[6];
    float* out = (float*)d_out;

    k_detect<<<1, 32>>>(eidx);
    k_init<<<4096, 256>>>(x, ef0);
    k_hist<<<Ee / 256, 256>>>(eidx, etyp);
    k_scan<<<1, 1024>>>();
    k_scatter<<<Ee / 256, 256>>>();

    for (int l = 0; l < Ll; l++) {
        k_rgef<<<1, 256>>>(theta, wr, l);
        k_gemm<<<dim3(Nn / 32, Tt), 256>>>(we, l);
        k_dots<<<(Tt * Nn * 32) / 256, 256>>>(theta, l);
        k_soft<<<Nn / 4, 128>>>();
        k_agg<<<Nn, 64>>>(out, l == Ll - 1, l < Ll - 1);
    }
}